// round 1
// baseline (speedup 1.0000x reference)
#include <cuda_runtime.h>
#include <cstdint>

// ---------------- problem constants ----------------
#define D_MODEL   1024
#define NUM_HEADS 16
#define HEAD_DIM  64
#define BATCH     2
#define SEQ       2048
#define M_TOT     (BATCH * SEQ)      // 4096
#define QKV_N     (3 * D_MODEL)      // 3072
#define LDS_      68                 // smem row stride (floats): 16B-aligned, conflict-reducing

// scratch (no cudaMalloc allowed)
__device__ float g_qkv[(size_t)M_TOT * QKV_N];      // [B,S,3D]  (H-major: h*192 + {q,k,v})
__device__ float g_attn[(size_t)M_TOT * D_MODEL];   // [B,H,S,hd] contiguous == reshape(B,S,D)

// ---------------- GEMM: C[M,N] = A[M,K] * Bw[N,K]^T + bias[N] ----------------
// 128x128x8 tiles, 256 threads, 8x8 micro-tile. Both operands K-contiguous.
__global__ __launch_bounds__(256, 2)
void gemm_bt_bias(const float* __restrict__ A, const float* __restrict__ Bw,
                  const float* __restrict__ bias, float* __restrict__ C,
                  int N, int K)
{
    __shared__ float As[8 * 128];
    __shared__ float Bs[8 * 128];
    const int tid = threadIdx.x;
    const int ty = tid >> 4, tx = tid & 15;
    const int row0 = blockIdx.y * 128;
    const int col0 = blockIdx.x * 128;
    const int lrow = tid >> 1;            // 0..127
    const int lk4  = (tid & 1) << 2;      // 0 or 4
    const float* Ag = A + (size_t)(row0 + lrow) * K + lk4;
    const float* Bg = Bw + (size_t)(col0 + lrow) * K + lk4;

    float acc[8][8];
#pragma unroll
    for (int i = 0; i < 8; i++)
#pragma unroll
        for (int j = 0; j < 8; j++) acc[i][j] = 0.f;

    for (int kc = 0; kc < K; kc += 8) {
        float4 a4 = *(const float4*)(Ag + kc);
        float4 b4 = *(const float4*)(Bg + kc);
        __syncthreads();
        As[(lk4 + 0) * 128 + lrow] = a4.x;
        As[(lk4 + 1) * 128 + lrow] = a4.y;
        As[(lk4 + 2) * 128 + lrow] = a4.z;
        As[(lk4 + 3) * 128 + lrow] = a4.w;
        Bs[(lk4 + 0) * 128 + lrow] = b4.x;
        Bs[(lk4 + 1) * 128 + lrow] = b4.y;
        Bs[(lk4 + 2) * 128 + lrow] = b4.z;
        Bs[(lk4 + 3) * 128 + lrow] = b4.w;
        __syncthreads();
#pragma unroll
        for (int k = 0; k < 8; k++) {
            float4 a0 = *(const float4*)&As[k * 128 + ty * 8];
            float4 a1 = *(const float4*)&As[k * 128 + ty * 8 + 4];
            float4 b0 = *(const float4*)&Bs[k * 128 + tx * 8];
            float4 b1 = *(const float4*)&Bs[k * 128 + tx * 8 + 4];
            float ar[8] = {a0.x, a0.y, a0.z, a0.w, a1.x, a1.y, a1.z, a1.w};
            float br[8] = {b0.x, b0.y, b0.z, b0.w, b1.x, b1.y, b1.z, b1.w};
#pragma unroll
            for (int i = 0; i < 8; i++)
#pragma unroll
                for (int j = 0; j < 8; j++) acc[i][j] += ar[i] * br[j];
        }
    }

    float bv[8];
#pragma unroll
    for (int j = 0; j < 8; j++) bv[j] = bias[col0 + tx * 8 + j];
#pragma unroll
    for (int i = 0; i < 8; i++) {
        float* crow = C + (size_t)(row0 + ty * 8 + i) * N + col0 + tx * 8;
        float4 r0 = make_float4(acc[i][0] + bv[0], acc[i][1] + bv[1],
                                acc[i][2] + bv[2], acc[i][3] + bv[3]);
        float4 r1 = make_float4(acc[i][4] + bv[4], acc[i][5] + bv[5],
                                acc[i][6] + bv[6], acc[i][7] + bv[7]);
        *(float4*)(crow) = r0;
        *(float4*)(crow + 4) = r1;
    }
}

// ---------------- flash attention (fp32, causal) ----------------
__device__ __forceinline__ float rmax16(float v) {
#pragma unroll
    for (int m = 8; m >= 1; m >>= 1) v = fmaxf(v, __shfl_xor_sync(0xffffffffu, v, m));
    return v;
}
__device__ __forceinline__ float rsum16(float v) {
#pragma unroll
    for (int m = 8; m >= 1; m >>= 1) v += __shfl_xor_sync(0xffffffffu, v, m);
    return v;
}

__global__ __launch_bounds__(256, 2)
void attn_kernel(const float* __restrict__ qkv, float* __restrict__ attn_out)
{
    extern __shared__ float smf[];
    float* Qt = smf;                    // [64][LDS_]  Qt[d][r], pre-scaled by 1/8
    float* Kt = smf + 64 * LDS_;        // [64][LDS_]  Kt[d][c]
    float* Vs = smf + 2 * 64 * LDS_;    // [64][LDS_]  Vs[key][d]
    float* Ps = smf + 3 * 64 * LDS_;    // [64][LDS_]  Ps[q][key]

    const int tid = threadIdx.x;
    const int ty = tid >> 4, tx = tid & 15;
    const int bh = blockIdx.y;
    const int b = bh >> 4, h = bh & 15;
    const int qt = (int)gridDim.x - 1 - (int)blockIdx.x;  // long CTAs first
    const int q0 = qt * 64;

    const float* base = qkv + (size_t)b * SEQ * QKV_N + (size_t)h * (3 * HEAD_DIM);
    const float SCALE = 0.125f;  // 1/sqrt(64)

    // load Q (transposed, pre-scaled)
#pragma unroll
    for (int i = 0; i < 4; i++) {
        int idx = tid + i * 256;
        int r = idx >> 4;
        int d4 = (idx & 15) << 2;
        float4 q4 = *(const float4*)(base + (size_t)(q0 + r) * QKV_N + d4);
        Qt[(d4 + 0) * LDS_ + r] = q4.x * SCALE;
        Qt[(d4 + 1) * LDS_ + r] = q4.y * SCALE;
        Qt[(d4 + 2) * LDS_ + r] = q4.z * SCALE;
        Qt[(d4 + 3) * LDS_ + r] = q4.w * SCALE;
    }

    float o[4][4];
    float mrun[4], lrun[4];
#pragma unroll
    for (int i = 0; i < 4; i++) {
        mrun[i] = -1e30f; lrun[i] = 0.f;
#pragma unroll
        for (int j = 0; j < 4; j++) o[i][j] = 0.f;
    }

    for (int jt = 0; jt <= qt; jt++) {
        const int k0 = jt * 64;
        // prefetch K/V tile into registers (hides gmem latency over the sync)
        float4 kk[4], vv[4];
#pragma unroll
        for (int i = 0; i < 4; i++) {
            int idx = tid + i * 256;
            int r = idx >> 4;
            int d4 = (idx & 15) << 2;
            const float* rp = base + (size_t)(k0 + r) * QKV_N + d4;
            kk[i] = *(const float4*)(rp + HEAD_DIM);
            vv[i] = *(const float4*)(rp + 2 * HEAD_DIM);
        }
        __syncthreads();   // previous tile's S / PV reads done
#pragma unroll
        for (int i = 0; i < 4; i++) {
            int idx = tid + i * 256;
            int r = idx >> 4;
            int d4 = (idx & 15) << 2;
            Kt[(d4 + 0) * LDS_ + r] = kk[i].x;
            Kt[(d4 + 1) * LDS_ + r] = kk[i].y;
            Kt[(d4 + 2) * LDS_ + r] = kk[i].z;
            Kt[(d4 + 3) * LDS_ + r] = kk[i].w;
            *(float4*)&Vs[r * LDS_ + d4] = vv[i];
        }
        __syncthreads();

        // S = (Q*scale) K^T   -- 64x64 tile, 4x4 per thread
        float s[4][4];
#pragma unroll
        for (int i = 0; i < 4; i++)
#pragma unroll
            for (int j = 0; j < 4; j++) s[i][j] = 0.f;

#pragma unroll 8
        for (int d = 0; d < HEAD_DIM; d++) {
            float4 qa = *(const float4*)&Qt[d * LDS_ + ty * 4];
            float4 kb = *(const float4*)&Kt[d * LDS_ + tx * 4];
            float aq[4] = {qa.x, qa.y, qa.z, qa.w};
            float bk[4] = {kb.x, kb.y, kb.z, kb.w};
#pragma unroll
            for (int i = 0; i < 4; i++)
#pragma unroll
                for (int j = 0; j < 4; j++) s[i][j] += aq[i] * bk[j];
        }

        // causal mask only on the diagonal tile
        if (jt == qt) {
#pragma unroll
            for (int i = 0; i < 4; i++) {
                int qg = q0 + ty * 4 + i;
#pragma unroll
                for (int j = 0; j < 4; j++) {
                    int kg = k0 + tx * 4 + j;
                    if (kg > qg) s[i][j] = -1e30f;
                }
            }
        }

        // online softmax per query row
#pragma unroll
        for (int i = 0; i < 4; i++) {
            float rm = fmaxf(fmaxf(s[i][0], s[i][1]), fmaxf(s[i][2], s[i][3]));
            rm = rmax16(rm);
            float mnew = fmaxf(mrun[i], rm);
            float alpha = __expf(mrun[i] - mnew);
            float rs = 0.f;
#pragma unroll
            for (int j = 0; j < 4; j++) {
                s[i][j] = __expf(s[i][j] - mnew);
                rs += s[i][j];
            }
            rs = rsum16(rs);
            lrun[i] = lrun[i] * alpha + rs;
            mrun[i] = mnew;
#pragma unroll
            for (int j = 0; j < 4; j++) o[i][j] *= alpha;
#pragma unroll
            for (int j = 0; j < 4; j++)
                Ps[(ty * 4 + i) * LDS_ + tx * 4 + j] = s[i][j];
        }
        __syncthreads();   // P visible

        // O += P V
#pragma unroll 8
        for (int k = 0; k < 64; k++) {
            float4 vb = *(const float4*)&Vs[k * LDS_ + tx * 4];
            float pv[4];
#pragma unroll
            for (int i = 0; i < 4; i++) pv[i] = Ps[(ty * 4 + i) * LDS_ + k];
#pragma unroll
            for (int i = 0; i < 4; i++) {
                o[i][0] += pv[i] * vb.x;
                o[i][1] += pv[i] * vb.y;
                o[i][2] += pv[i] * vb.z;
                o[i][3] += pv[i] * vb.w;
            }
        }
    }

    // normalize + write [B,H,S,hd]
#pragma unroll
    for (int i = 0; i < 4; i++) {
        float inv = 1.0f / lrun[i];
        int r = q0 + ty * 4 + i;
        float4 w = make_float4(o[i][0] * inv, o[i][1] * inv, o[i][2] * inv, o[i][3] * inv);
        *(float4*)&attn_out[(((size_t)b * NUM_HEADS + h) * SEQ + r) * HEAD_DIM + tx * 4] = w;
    }
}

// ---------------- launch ----------------
extern "C" void kernel_launch(void* const* d_in, const int* in_sizes, int n_in,
                              void* d_out, int out_size)
{
    const float* x    = (const float*)d_in[0];
    const float* Wqkv = (const float*)d_in[1];
    const float* bqkv = (const float*)d_in[2];
    const float* Wo   = (const float*)d_in[3];
    const float* bo   = (const float*)d_in[4];
    float* out = (float*)d_out;

    float* qkv_ptr = nullptr;
    float* attn_ptr = nullptr;
    cudaGetSymbolAddress((void**)&qkv_ptr, g_qkv);
    cudaGetSymbolAddress((void**)&attn_ptr, g_attn);

    const int attn_smem = 4 * 64 * LDS_ * sizeof(float);  // 69632 B
    cudaFuncSetAttribute(attn_kernel, cudaFuncAttributeMaxDynamicSharedMemorySize, attn_smem);

    // 1) qkv = x @ Wqkv^T + bqkv
    gemm_bt_bias<<<dim3(QKV_N / 128, M_TOT / 128), 256>>>(x, Wqkv, bqkv, qkv_ptr, QKV_N, D_MODEL);
    // 2) causal flash attention
    attn_kernel<<<dim3(SEQ / 64, BATCH * NUM_HEADS), 256, attn_smem>>>(qkv_ptr, attn_ptr);
    // 3) out = attn @ Wo^T + bo
    gemm_bt_bias<<<dim3(D_MODEL / 128, M_TOT / 128), 256>>>(attn_ptr, Wo, bo, out, D_MODEL, D_MODEL);
}

// round 3
// speedup vs baseline: 1.6772x; 1.6772x over previous
#include <cuda_runtime.h>
#include <cstdint>

// ---------------- problem constants ----------------
#define D_MODEL   1024
#define NUM_HEADS 16
#define HEAD_DIM  64
#define BATCH     2
#define SEQ       2048
#define M_TOT     (BATCH * SEQ)      // 4096
#define QKV_N     (3 * D_MODEL)      // 3072
#define LDS_      68                 // attention smem row stride

// scratch (no cudaMalloc allowed)
__device__ float g_qkv[(size_t)M_TOT * QKV_N];      // [B,S,3D]
__device__ float g_attn[(size_t)M_TOT * D_MODEL];   // [B,H,S,hd] == reshape(B,S,D)

// ---------------- tf32 helpers ----------------
__device__ __forceinline__ uint32_t f2tf32(float f) {
    uint32_t u;
    asm("cvt.rna.tf32.f32 %0, %1;" : "=r"(u) : "f"(f));
    return u;
}
__device__ __forceinline__ void mma_tf32(float c[4], uint32_t a0, uint32_t a1,
                                         uint32_t a2, uint32_t a3,
                                         uint32_t b0, uint32_t b1) {
    asm volatile(
        "mma.sync.aligned.m16n8k8.row.col.f32.tf32.tf32.f32 "
        "{%0,%1,%2,%3}, {%4,%5,%6,%7}, {%8,%9}, {%0,%1,%2,%3};\n"
        : "+f"(c[0]), "+f"(c[1]), "+f"(c[2]), "+f"(c[3])
        : "r"(a0), "r"(a1), "r"(a2), "r"(a3), "r"(b0), "r"(b1));
}

// ---------------- tf32 tensor-core GEMM: C[M,N] = A[M,K] * Bw[N,K]^T + bias ----------------
// 128x128x32 CTA tile, 256 threads (8 warps), warp tile 64x32 (4x4 m16n8k8).
// Both operands row-major [.][K] in smem, stride 36 (conflict-free for both
// the float4 staging stores and the scalar fragment loads).
#define BM 128
#define BN 128
#define BK 32
#define LDT 36

__global__ __launch_bounds__(256)
void gemm_tf32(const float* __restrict__ A, const float* __restrict__ Bw,
               const float* __restrict__ bias, float* __restrict__ C,
               int N, int K)
{
    __shared__ float As[BM * LDT];
    __shared__ float Bs[BN * LDT];

    const int tid  = threadIdx.x;
    const int lane = tid & 31;
    const int wid  = tid >> 5;
    const int g = lane >> 2;      // groupID 0..7
    const int t = lane & 3;       // thread-in-group 0..3
    const int wm = wid >> 2;      // 0..1  -> 64 rows each
    const int wn = wid & 3;       // 0..3  -> 32 cols each
    const int row0 = blockIdx.y * BM;
    const int col0 = blockIdx.x * BN;

    // staging loader: kg = float4 index along K (0..7), lr = row 0..31 (+i*32)
    const int kg = tid & 7;
    const int lr = tid >> 3;
    const float* Ag = A  + (size_t)(row0 + lr) * K + kg * 4;
    const float* Bg = Bw + (size_t)(col0 + lr) * K + kg * 4;

    float c[4][4][4];
#pragma unroll
    for (int mt = 0; mt < 4; mt++)
#pragma unroll
        for (int nt = 0; nt < 4; nt++)
#pragma unroll
            for (int r = 0; r < 4; r++) c[mt][nt][r] = 0.f;

    const float* Awp = &As[(wm * 64) * LDT];
    const float* Bwp = &Bs[(wn * 32) * LDT];

    for (int kp = 0; kp < K; kp += BK) {
        // prefetch into registers (overlaps previous compute), round to tf32
        float4 av[4], bv[4];
#pragma unroll
        for (int i = 0; i < 4; i++) {
            av[i] = *(const float4*)(Ag + (size_t)i * 32 * K + kp);
            bv[i] = *(const float4*)(Bg + (size_t)i * 32 * K + kp);
        }
#pragma unroll
        for (int i = 0; i < 4; i++) {
            av[i].x = __uint_as_float(f2tf32(av[i].x));
            av[i].y = __uint_as_float(f2tf32(av[i].y));
            av[i].z = __uint_as_float(f2tf32(av[i].z));
            av[i].w = __uint_as_float(f2tf32(av[i].w));
            bv[i].x = __uint_as_float(f2tf32(bv[i].x));
            bv[i].y = __uint_as_float(f2tf32(bv[i].y));
            bv[i].z = __uint_as_float(f2tf32(bv[i].z));
            bv[i].w = __uint_as_float(f2tf32(bv[i].w));
        }
        __syncthreads();   // previous panel fully consumed
#pragma unroll
        for (int i = 0; i < 4; i++) {
            *(float4*)&As[(lr + i * 32) * LDT + kg * 4] = av[i];
            *(float4*)&Bs[(lr + i * 32) * LDT + kg * 4] = bv[i];
        }
        __syncthreads();

#pragma unroll
        for (int kq = 0; kq < BK; kq += 8) {
            uint32_t af[4][4], bf[4][2];
#pragma unroll
            for (int mt = 0; mt < 4; mt++) {
                const float* ap = Awp + (mt * 16 + g) * LDT + kq + t;
                af[mt][0] = __float_as_uint(ap[0]);
                af[mt][1] = __float_as_uint(ap[8 * LDT]);
                af[mt][2] = __float_as_uint(ap[4]);
                af[mt][3] = __float_as_uint(ap[8 * LDT + 4]);
            }
#pragma unroll
            for (int nt = 0; nt < 4; nt++) {
                const float* bp = Bwp + (nt * 8 + g) * LDT + kq + t;
                bf[nt][0] = __float_as_uint(bp[0]);
                bf[nt][1] = __float_as_uint(bp[4]);
            }
#pragma unroll
            for (int mt = 0; mt < 4; mt++)
#pragma unroll
                for (int nt = 0; nt < 4; nt++)
                    mma_tf32(c[mt][nt], af[mt][0], af[mt][1], af[mt][2], af[mt][3],
                             bf[nt][0], bf[nt][1]);
        }
    }

    // epilogue: bias + store (float2 per row-pair)
#pragma unroll
    for (int mt = 0; mt < 4; mt++) {
        int row = row0 + wm * 64 + mt * 16 + g;
#pragma unroll
        for (int nt = 0; nt < 4; nt++) {
            int col = col0 + wn * 32 + nt * 8 + 2 * t;
            float b0 = bias[col], b1 = bias[col + 1];
            float2 v0 = make_float2(c[mt][nt][0] + b0, c[mt][nt][1] + b1);
            float2 v1 = make_float2(c[mt][nt][2] + b0, c[mt][nt][3] + b1);
            *(float2*)&C[(size_t)row * N + col] = v0;
            *(float2*)&C[(size_t)(row + 8) * N + col] = v1;
        }
    }
}

// ---------------- flash attention (fp32, causal) ----------------
__device__ __forceinline__ float rmax16(float v) {
#pragma unroll
    for (int m = 8; m >= 1; m >>= 1) v = fmaxf(v, __shfl_xor_sync(0xffffffffu, v, m));
    return v;
}
__device__ __forceinline__ float rsum16(float v) {
#pragma unroll
    for (int m = 8; m >= 1; m >>= 1) v += __shfl_xor_sync(0xffffffffu, v, m);
    return v;
}

__global__ __launch_bounds__(256, 2)
void attn_kernel(const float* __restrict__ qkv, float* __restrict__ attn_out)
{
    extern __shared__ float smf[];
    float* Qt = smf;                    // [64][LDS_]  Qt[d][r], pre-scaled
    float* Kt = smf + 64 * LDS_;        // [64][LDS_]  Kt[d][c]
    float* Vs = smf + 2 * 64 * LDS_;    // [64][LDS_]  Vs[key][d]
    float* Ps = smf + 3 * 64 * LDS_;    // [64][LDS_]  Ps[q][key]

    const int tid = threadIdx.x;
    const int ty = tid >> 4, tx = tid & 15;
    const int bh = blockIdx.y;
    const int b = bh >> 4, h = bh & 15;
    const int qt = (int)gridDim.x - 1 - (int)blockIdx.x;  // long CTAs first
    const int q0 = qt * 64;

    const float* base = qkv + (size_t)b * SEQ * QKV_N + (size_t)h * (3 * HEAD_DIM);
    const float SCALE = 0.125f;

#pragma unroll
    for (int i = 0; i < 4; i++) {
        int idx = tid + i * 256;
        int r = idx >> 4;
        int d4 = (idx & 15) << 2;
        float4 q4 = *(const float4*)(base + (size_t)(q0 + r) * QKV_N + d4);
        Qt[(d4 + 0) * LDS_ + r] = q4.x * SCALE;
        Qt[(d4 + 1) * LDS_ + r] = q4.y * SCALE;
        Qt[(d4 + 2) * LDS_ + r] = q4.z * SCALE;
        Qt[(d4 + 3) * LDS_ + r] = q4.w * SCALE;
    }

    float o[4][4];
    float mrun[4], lrun[4];
#pragma unroll
    for (int i = 0; i < 4; i++) {
        mrun[i] = -1e30f; lrun[i] = 0.f;
#pragma unroll
        for (int j = 0; j < 4; j++) o[i][j] = 0.f;
    }

    for (int jt = 0; jt <= qt; jt++) {
        const int k0 = jt * 64;
        float4 kk[4], vv[4];
#pragma unroll
        for (int i = 0; i < 4; i++) {
            int idx = tid + i * 256;
            int r = idx >> 4;
            int d4 = (idx & 15) << 2;
            const float* rp = base + (size_t)(k0 + r) * QKV_N + d4;
            kk[i] = *(const float4*)(rp + HEAD_DIM);
            vv[i] = *(const float4*)(rp + 2 * HEAD_DIM);
        }
        __syncthreads();
#pragma unroll
        for (int i = 0; i < 4; i++) {
            int idx = tid + i * 256;
            int r = idx >> 4;
            int d4 = (idx & 15) << 2;
            Kt[(d4 + 0) * LDS_ + r] = kk[i].x;
            Kt[(d4 + 1) * LDS_ + r] = kk[i].y;
            Kt[(d4 + 2) * LDS_ + r] = kk[i].z;
            Kt[(d4 + 3) * LDS_ + r] = kk[i].w;
            *(float4*)&Vs[r * LDS_ + d4] = vv[i];
        }
        __syncthreads();

        float s[4][4];
#pragma unroll
        for (int i = 0; i < 4; i++)
#pragma unroll
            for (int j = 0; j < 4; j++) s[i][j] = 0.f;

#pragma unroll 8
        for (int d = 0; d < HEAD_DIM; d++) {
            float4 qa = *(const float4*)&Qt[d * LDS_ + ty * 4];
            float4 kb = *(const float4*)&Kt[d * LDS_ + tx * 4];
            float aq[4] = {qa.x, qa.y, qa.z, qa.w};
            float bk[4] = {kb.x, kb.y, kb.z, kb.w};
#pragma unroll
            for (int i = 0; i < 4; i++)
#pragma unroll
                for (int j = 0; j < 4; j++) s[i][j] += aq[i] * bk[j];
        }

        if (jt == qt) {
#pragma unroll
            for (int i = 0; i < 4; i++) {
                int qg = q0 + ty * 4 + i;
#pragma unroll
                for (int j = 0; j < 4; j++) {
                    int kg = k0 + tx * 4 + j;
                    if (kg > qg) s[i][j] = -1e30f;
                }
            }
        }

#pragma unroll
        for (int i = 0; i < 4; i++) {
            float rm = fmaxf(fmaxf(s[i][0], s[i][1]), fmaxf(s[i][2], s[i][3]));
            rm = rmax16(rm);
            float mnew = fmaxf(mrun[i], rm);
            float alpha = __expf(mrun[i] - mnew);
            float rs = 0.f;
#pragma unroll
            for (int j = 0; j < 4; j++) {
                s[i][j] = __expf(s[i][j] - mnew);
                rs += s[i][j];
            }
            rs = rsum16(rs);
            lrun[i] = lrun[i] * alpha + rs;
            mrun[i] = mnew;
#pragma unroll
            for (int j = 0; j < 4; j++) o[i][j] *= alpha;
#pragma unroll
            for (int j = 0; j < 4; j++)
                Ps[(ty * 4 + i) * LDS_ + tx * 4 + j] = s[i][j];
        }
        __syncthreads();

#pragma unroll 8
        for (int k = 0; k < 64; k++) {
            float4 vb = *(const float4*)&Vs[k * LDS_ + tx * 4];
            float pv[4];
#pragma unroll
            for (int i = 0; i < 4; i++) pv[i] = Ps[(ty * 4 + i) * LDS_ + k];
#pragma unroll
            for (int i = 0; i < 4; i++) {
                o[i][0] += pv[i] * vb.x;
                o[i][1] += pv[i] * vb.y;
                o[i][2] += pv[i] * vb.z;
                o[i][3] += pv[i] * vb.w;
            }
        }
    }

#pragma unroll
    for (int i = 0; i < 4; i++) {
        float inv = 1.0f / lrun[i];
        int r = q0 + ty * 4 + i;
        float4 w = make_float4(o[i][0] * inv, o[i][1] * inv, o[i][2] * inv, o[i][3] * inv);
        *(float4*)&attn_out[(((size_t)b * NUM_HEADS + h) * SEQ + r) * HEAD_DIM + tx * 4] = w;
    }
}

// ---------------- launch ----------------
extern "C" void kernel_launch(void* const* d_in, const int* in_sizes, int n_in,
                              void* d_out, int out_size)
{
    const float* x    = (const float*)d_in[0];
    const float* Wqkv = (const float*)d_in[1];
    const float* bqkv = (const float*)d_in[2];
    const float* Wo   = (const float*)d_in[3];
    const float* bo   = (const float*)d_in[4];
    float* out = (float*)d_out;

    float* qkv_ptr = nullptr;
    float* attn_ptr = nullptr;
    cudaGetSymbolAddress((void**)&qkv_ptr, g_qkv);
    cudaGetSymbolAddress((void**)&attn_ptr, g_attn);

    const int attn_smem = 4 * 64 * LDS_ * sizeof(float);  // 69632 B
    cudaFuncSetAttribute(attn_kernel, cudaFuncAttributeMaxDynamicSharedMemorySize, attn_smem);

    // 1) qkv = x @ Wqkv^T + bqkv   (tf32 tensor cores)
    gemm_tf32<<<dim3(QKV_N / BN, M_TOT / BM), 256>>>(x, Wqkv, bqkv, qkv_ptr, QKV_N, D_MODEL);
    // 2) causal flash attention (fp32)
    attn_kernel<<<dim3(SEQ / 64, BATCH * NUM_HEADS), 256, attn_smem>>>(qkv_ptr, attn_ptr);
    // 3) out = attn @ Wo^T + bo    (tf32 tensor cores)
    gemm_tf32<<<dim3(D_MODEL / BN, M_TOT / BM), 256>>>(attn_ptr, Wo, bo, out, D_MODEL, D_MODEL);
}

// round 4
// speedup vs baseline: 1.9247x; 1.1475x over previous
#include <cuda_runtime.h>
#include <cstdint>

// ---------------- problem constants ----------------
#define D_MODEL   1024
#define NUM_HEADS 16
#define HEAD_DIM  64
#define BATCH     2
#define SEQ       2048
#define M_TOT     (BATCH * SEQ)      // 4096
#define QKV_N     (3 * D_MODEL)      // 3072

// scratch (no cudaMalloc allowed)
__device__ float g_qkv[(size_t)M_TOT * QKV_N];      // [B,S,3D]
__device__ float g_attn[(size_t)M_TOT * D_MODEL];   // [B,H,S,hd] == reshape(B,S,D)

// ---------------- tf32 helpers ----------------
__device__ __forceinline__ uint32_t f2tf32(float f) {
    uint32_t u;
    asm("cvt.rna.tf32.f32 %0, %1;" : "=r"(u) : "f"(f));
    return u;
}
__device__ __forceinline__ void mma_tf32(float c[4], uint32_t a0, uint32_t a1,
                                         uint32_t a2, uint32_t a3,
                                         uint32_t b0, uint32_t b1) {
    asm volatile(
        "mma.sync.aligned.m16n8k8.row.col.f32.tf32.tf32.f32 "
        "{%0,%1,%2,%3}, {%4,%5,%6,%7}, {%8,%9}, {%0,%1,%2,%3};\n"
        : "+f"(c[0]), "+f"(c[1]), "+f"(c[2]), "+f"(c[3])
        : "r"(a0), "r"(a1), "r"(a2), "r"(a3), "r"(b0), "r"(b1));
}

// ---------------- tf32 tensor-core GEMM (unchanged from R3) ----------------
#define BM 128
#define BN 128
#define BK 32
#define LDT 36

__global__ __launch_bounds__(256)
void gemm_tf32(const float* __restrict__ A, const float* __restrict__ Bw,
               const float* __restrict__ bias, float* __restrict__ C,
               int N, int K)
{
    __shared__ float As[BM * LDT];
    __shared__ float Bs[BN * LDT];

    const int tid  = threadIdx.x;
    const int lane = tid & 31;
    const int wid  = tid >> 5;
    const int g = lane >> 2;
    const int t = lane & 3;
    const int wm = wid >> 2;
    const int wn = wid & 3;
    const int row0 = blockIdx.y * BM;
    const int col0 = blockIdx.x * BN;

    const int kg = tid & 7;
    const int lr = tid >> 3;
    const float* Ag = A  + (size_t)(row0 + lr) * K + kg * 4;
    const float* Bg = Bw + (size_t)(col0 + lr) * K + kg * 4;

    float c[4][4][4];
#pragma unroll
    for (int mt = 0; mt < 4; mt++)
#pragma unroll
        for (int nt = 0; nt < 4; nt++)
#pragma unroll
            for (int r = 0; r < 4; r++) c[mt][nt][r] = 0.f;

    const float* Awp = &As[(wm * 64) * LDT];
    const float* Bwp = &Bs[(wn * 32) * LDT];

    for (int kp = 0; kp < K; kp += BK) {
        float4 av[4], bv[4];
#pragma unroll
        for (int i = 0; i < 4; i++) {
            av[i] = *(const float4*)(Ag + (size_t)i * 32 * K + kp);
            bv[i] = *(const float4*)(Bg + (size_t)i * 32 * K + kp);
        }
#pragma unroll
        for (int i = 0; i < 4; i++) {
            av[i].x = __uint_as_float(f2tf32(av[i].x));
            av[i].y = __uint_as_float(f2tf32(av[i].y));
            av[i].z = __uint_as_float(f2tf32(av[i].z));
            av[i].w = __uint_as_float(f2tf32(av[i].w));
            bv[i].x = __uint_as_float(f2tf32(bv[i].x));
            bv[i].y = __uint_as_float(f2tf32(bv[i].y));
            bv[i].z = __uint_as_float(f2tf32(bv[i].z));
            bv[i].w = __uint_as_float(f2tf32(bv[i].w));
        }
        __syncthreads();
#pragma unroll
        for (int i = 0; i < 4; i++) {
            *(float4*)&As[(lr + i * 32) * LDT + kg * 4] = av[i];
            *(float4*)&Bs[(lr + i * 32) * LDT + kg * 4] = bv[i];
        }
        __syncthreads();

#pragma unroll
        for (int kq = 0; kq < BK; kq += 8) {
            uint32_t af[4][4], bf[4][2];
#pragma unroll
            for (int mt = 0; mt < 4; mt++) {
                const float* ap = Awp + (mt * 16 + g) * LDT + kq + t;
                af[mt][0] = __float_as_uint(ap[0]);
                af[mt][1] = __float_as_uint(ap[8 * LDT]);
                af[mt][2] = __float_as_uint(ap[4]);
                af[mt][3] = __float_as_uint(ap[8 * LDT + 4]);
            }
#pragma unroll
            for (int nt = 0; nt < 4; nt++) {
                const float* bp = Bwp + (nt * 8 + g) * LDT + kq + t;
                bf[nt][0] = __float_as_uint(bp[0]);
                bf[nt][1] = __float_as_uint(bp[4]);
            }
#pragma unroll
            for (int mt = 0; mt < 4; mt++)
#pragma unroll
                for (int nt = 0; nt < 4; nt++)
                    mma_tf32(c[mt][nt], af[mt][0], af[mt][1], af[mt][2], af[mt][3],
                             bf[nt][0], bf[nt][1]);
        }
    }

#pragma unroll
    for (int mt = 0; mt < 4; mt++) {
        int row = row0 + wm * 64 + mt * 16 + g;
#pragma unroll
        for (int nt = 0; nt < 4; nt++) {
            int col = col0 + wn * 32 + nt * 8 + 2 * t;
            float b0 = bias[col], b1 = bias[col + 1];
            float2 v0 = make_float2(c[mt][nt][0] + b0, c[mt][nt][1] + b1);
            float2 v1 = make_float2(c[mt][nt][2] + b0, c[mt][nt][3] + b1);
            *(float2*)&C[(size_t)row * N + col] = v0;
            *(float2*)&C[(size_t)(row + 8) * N + col] = v1;
        }
    }
}

// ---------------- tensor-core flash attention (tf32 3-term split, causal) ----------------
// CTA: 128 queries x 64-key tiles, 8 warps (16 rows each).
#define ALD 68
#define VLD 72
#define SM_Q 0
#define SM_K (128 * ALD)
#define SM_V (SM_K + 64 * ALD)
#define SM_P (SM_V + 64 * VLD)
#define SM_TOT_F (SM_P + 128 * ALD)   // 26368 floats = 105472 bytes

__global__ __launch_bounds__(256, 2)
void attn_tc(const float* __restrict__ qkv, float* __restrict__ attn_out)
{
    extern __shared__ float sm[];
    float* Qs = sm + SM_Q;   // [128][ALD] fp32, pre-scaled by 1/8*log2e
    float* Ks = sm + SM_K;   // [64][ALD]
    float* Vs = sm + SM_V;   // [64][VLD]
    float* Ps = sm + SM_P;   // [128][ALD]

    const int tid  = threadIdx.x;
    const int lane = tid & 31;
    const int w = tid >> 5;
    const int g = lane >> 2;
    const int t = lane & 3;
    const int b = blockIdx.y >> 4, h = blockIdx.y & 15;
    const int qt = (int)gridDim.x - 1 - (int)blockIdx.x;   // heavy CTAs first
    const int q0 = qt * 128;
    const float* base = qkv + (size_t)b * SEQ * QKV_N + h * (3 * HEAD_DIM);
    const float SC = 0.125f * 1.4426950408889634f;   // 1/sqrt(hd) * log2(e)

    // load Q tile (pre-scaled into exp2 domain)
#pragma unroll
    for (int i = 0; i < 8; i++) {
        int idx = tid + i * 256;
        int r = idx >> 4, c4 = (idx & 15) << 2;
        float4 q = *(const float4*)(base + (size_t)(q0 + r) * QKV_N + c4);
        q.x *= SC; q.y *= SC; q.z *= SC; q.w *= SC;
        *(float4*)&Qs[r * ALD + c4] = q;
    }

    float o[8][4];
#pragma unroll
    for (int nt = 0; nt < 8; nt++)
#pragma unroll
        for (int r = 0; r < 4; r++) o[nt][r] = 0.f;
    float m0 = -1e30f, m1 = -1e30f, l0 = 0.f, l1 = 0.f;

    const int myrow = q0 + w * 16;
    const int rowg0 = myrow + g, rowg1 = myrow + g + 8;
    const int nkt = qt * 2 + 2;

    for (int j = 0; j < nkt; j++) {
        const int k0 = j * 64;
        // register prefetch of K/V tile
        float4 kk[4], vv[4];
#pragma unroll
        for (int i = 0; i < 4; i++) {
            int idx = tid + i * 256;
            int r = idx >> 4, c4 = (idx & 15) << 2;
            const float* rp = base + (size_t)(k0 + r) * QKV_N + c4;
            kk[i] = *(const float4*)(rp + HEAD_DIM);
            vv[i] = *(const float4*)(rp + 2 * HEAD_DIM);
        }
        __syncthreads();   // previous tile fully consumed
#pragma unroll
        for (int i = 0; i < 4; i++) {
            int idx = tid + i * 256;
            int r = idx >> 4, c4 = (idx & 15) << 2;
            *(float4*)&Ks[r * ALD + c4] = kk[i];
            *(float4*)&Vs[r * VLD + c4] = vv[i];
        }
        __syncthreads();

        if (k0 <= myrow + 15) {          // not fully masked for this warp
            // ---- S = Q K^T (3-term tf32 split, fp32 accum) ----
            float s[8][4];
#pragma unroll
            for (int nt = 0; nt < 8; nt++)
#pragma unroll
                for (int r = 0; r < 4; r++) s[nt][r] = 0.f;

#pragma unroll
            for (int kq = 0; kq < 8; kq++) {
                const int kc = kq * 8;
                float a0 = Qs[(w * 16 + g) * ALD + kc + t];
                float a1 = Qs[(w * 16 + g + 8) * ALD + kc + t];
                float a2 = Qs[(w * 16 + g) * ALD + kc + t + 4];
                float a3 = Qs[(w * 16 + g + 8) * ALD + kc + t + 4];
                uint32_t ah0 = f2tf32(a0), ah1 = f2tf32(a1), ah2 = f2tf32(a2), ah3 = f2tf32(a3);
                uint32_t al0 = f2tf32(a0 - __uint_as_float(ah0));
                uint32_t al1 = f2tf32(a1 - __uint_as_float(ah1));
                uint32_t al2 = f2tf32(a2 - __uint_as_float(ah2));
                uint32_t al3 = f2tf32(a3 - __uint_as_float(ah3));
#pragma unroll
                for (int nt = 0; nt < 8; nt++) {
                    float b0 = Ks[(nt * 8 + g) * ALD + kc + t];
                    float b1 = Ks[(nt * 8 + g) * ALD + kc + t + 4];
                    uint32_t bh0 = f2tf32(b0), bh1 = f2tf32(b1);
                    uint32_t bl0 = f2tf32(b0 - __uint_as_float(bh0));
                    uint32_t bl1 = f2tf32(b1 - __uint_as_float(bh1));
                    mma_tf32(s[nt], ah0, ah1, ah2, ah3, bh0, bh1);
                    mma_tf32(s[nt], al0, al1, al2, al3, bh0, bh1);
                    mma_tf32(s[nt], ah0, ah1, ah2, ah3, bl0, bl1);
                }
            }

            // ---- causal mask (diagonal-straddling tiles only) ----
            if (k0 + 63 > myrow) {
#pragma unroll
                for (int nt = 0; nt < 8; nt++) {
                    int c = k0 + nt * 8 + 2 * t;
                    if (c > rowg0)     s[nt][0] = -1e30f;
                    if (c + 1 > rowg0) s[nt][1] = -1e30f;
                    if (c > rowg1)     s[nt][2] = -1e30f;
                    if (c + 1 > rowg1) s[nt][3] = -1e30f;
                }
            }

            // ---- online softmax (exp2 domain) ----
            float rm0 = -1e30f, rm1 = -1e30f;
#pragma unroll
            for (int nt = 0; nt < 8; nt++) {
                rm0 = fmaxf(rm0, fmaxf(s[nt][0], s[nt][1]));
                rm1 = fmaxf(rm1, fmaxf(s[nt][2], s[nt][3]));
            }
            rm0 = fmaxf(rm0, __shfl_xor_sync(0xffffffffu, rm0, 1));
            rm0 = fmaxf(rm0, __shfl_xor_sync(0xffffffffu, rm0, 2));
            rm1 = fmaxf(rm1, __shfl_xor_sync(0xffffffffu, rm1, 1));
            rm1 = fmaxf(rm1, __shfl_xor_sync(0xffffffffu, rm1, 2));
            float mn0 = fmaxf(m0, rm0), mn1 = fmaxf(m1, rm1);
            float alp0 = exp2f(m0 - mn0), alp1 = exp2f(m1 - mn1);
            float rs0 = 0.f, rs1 = 0.f;
#pragma unroll
            for (int nt = 0; nt < 8; nt++) {
                s[nt][0] = exp2f(s[nt][0] - mn0);
                s[nt][1] = exp2f(s[nt][1] - mn0);
                s[nt][2] = exp2f(s[nt][2] - mn1);
                s[nt][3] = exp2f(s[nt][3] - mn1);
                rs0 += s[nt][0] + s[nt][1];
                rs1 += s[nt][2] + s[nt][3];
                *(float2*)&Ps[(w * 16 + g) * ALD + nt * 8 + 2 * t] = make_float2(s[nt][0], s[nt][1]);
                *(float2*)&Ps[(w * 16 + g + 8) * ALD + nt * 8 + 2 * t] = make_float2(s[nt][2], s[nt][3]);
            }
            rs0 += __shfl_xor_sync(0xffffffffu, rs0, 1);
            rs0 += __shfl_xor_sync(0xffffffffu, rs0, 2);
            rs1 += __shfl_xor_sync(0xffffffffu, rs1, 1);
            rs1 += __shfl_xor_sync(0xffffffffu, rs1, 2);
            l0 = l0 * alp0 + rs0;  l1 = l1 * alp1 + rs1;
            m0 = mn0;  m1 = mn1;
#pragma unroll
            for (int nt = 0; nt < 8; nt++) {
                o[nt][0] *= alp0; o[nt][1] *= alp0;
                o[nt][2] *= alp1; o[nt][3] *= alp1;
            }
            __syncwarp();   // P stores visible to warp

            // ---- O += P V (3-term tf32 split) ----
#pragma unroll
            for (int kq = 0; kq < 8; kq++) {
                const int kc = kq * 8;
                float a0 = Ps[(w * 16 + g) * ALD + kc + t];
                float a1 = Ps[(w * 16 + g + 8) * ALD + kc + t];
                float a2 = Ps[(w * 16 + g) * ALD + kc + t + 4];
                float a3 = Ps[(w * 16 + g + 8) * ALD + kc + t + 4];
                uint32_t ah0 = f2tf32(a0), ah1 = f2tf32(a1), ah2 = f2tf32(a2), ah3 = f2tf32(a3);
                uint32_t al0 = f2tf32(a0 - __uint_as_float(ah0));
                uint32_t al1 = f2tf32(a1 - __uint_as_float(ah1));
                uint32_t al2 = f2tf32(a2 - __uint_as_float(ah2));
                uint32_t al3 = f2tf32(a3 - __uint_as_float(ah3));
#pragma unroll
                for (int nt = 0; nt < 8; nt++) {
                    float b0 = Vs[(kc + t) * VLD + nt * 8 + g];
                    float b1 = Vs[(kc + t + 4) * VLD + nt * 8 + g];
                    uint32_t bh0 = f2tf32(b0), bh1 = f2tf32(b1);
                    uint32_t bl0 = f2tf32(b0 - __uint_as_float(bh0));
                    uint32_t bl1 = f2tf32(b1 - __uint_as_float(bh1));
                    mma_tf32(o[nt], ah0, ah1, ah2, ah3, bh0, bh1);
                    mma_tf32(o[nt], al0, al1, al2, al3, bh0, bh1);
                    mma_tf32(o[nt], ah0, ah1, ah2, ah3, bl0, bl1);
                }
            }
            __syncwarp();   // PV reads done before next tile's P stores
        }
    }

    // ---- normalize + write [B,H,S,hd] ----
    float inv0 = 1.0f / l0, inv1 = 1.0f / l1;
    float* op = attn_out + ((size_t)b * NUM_HEADS + h) * SEQ * HEAD_DIM;
#pragma unroll
    for (int nt = 0; nt < 8; nt++) {
        int c = nt * 8 + 2 * t;
        *(float2*)&op[(size_t)rowg0 * HEAD_DIM + c] =
            make_float2(o[nt][0] * inv0, o[nt][1] * inv0);
        *(float2*)&op[(size_t)rowg1 * HEAD_DIM + c] =
            make_float2(o[nt][2] * inv1, o[nt][3] * inv1);
    }
}

// ---------------- launch ----------------
extern "C" void kernel_launch(void* const* d_in, const int* in_sizes, int n_in,
                              void* d_out, int out_size)
{
    const float* x    = (const float*)d_in[0];
    const float* Wqkv = (const float*)d_in[1];
    const float* bqkv = (const float*)d_in[2];
    const float* Wo   = (const float*)d_in[3];
    const float* bo   = (const float*)d_in[4];
    float* out = (float*)d_out;

    float* qkv_ptr = nullptr;
    float* attn_ptr = nullptr;
    cudaGetSymbolAddress((void**)&qkv_ptr, g_qkv);
    cudaGetSymbolAddress((void**)&attn_ptr, g_attn);

    const int attn_smem = SM_TOT_F * sizeof(float);   // 105472 B
    cudaFuncSetAttribute(attn_tc, cudaFuncAttributeMaxDynamicSharedMemorySize, attn_smem);

    // 1) qkv = x @ Wqkv^T + bqkv   (tf32 tensor cores)
    gemm_tf32<<<dim3(QKV_N / BN, M_TOT / BM), 256>>>(x, Wqkv, bqkv, qkv_ptr, QKV_N, D_MODEL);
    // 2) causal flash attention (tf32 tensor cores, 3-term split)
    attn_tc<<<dim3(SEQ / 128, BATCH * NUM_HEADS), 256, attn_smem>>>(qkv_ptr, attn_ptr);
    // 3) out = attn @ Wo^T + bo    (tf32 tensor cores)
    gemm_tf32<<<dim3(D_MODEL / BN, M_TOT / BM), 256>>>(attn_ptr, Wo, bo, out, D_MODEL, D_MODEL);
}

// round 7
// speedup vs baseline: 3.2957x; 1.7124x over previous
#include <cuda_runtime.h>
#include <cuda_fp16.h>
#include <cstdint>

// ---------------- problem constants ----------------
#define D_MODEL   1024
#define NUM_HEADS 16
#define HEAD_DIM  64
#define BATCH     2
#define SEQ       2048
#define M_TOT     (BATCH * SEQ)      // 4096
#define QKV_N     (3 * D_MODEL)      // 3072

// scratch (no cudaMalloc allowed)
__device__ float g_qkv[(size_t)M_TOT * QKV_N];      // [B,S,3D]
__device__ float g_attn[(size_t)M_TOT * D_MODEL];   // [B,H,S,hd] == reshape(B,S,D)

// ---------------- tf32 helpers (GEMM) ----------------
__device__ __forceinline__ uint32_t f2tf32(float f) {
    uint32_t u;
    asm("cvt.rna.tf32.f32 %0, %1;" : "=r"(u) : "f"(f));
    return u;
}
__device__ __forceinline__ void mma_tf32(float c[4], uint32_t a0, uint32_t a1,
                                         uint32_t a2, uint32_t a3,
                                         uint32_t b0, uint32_t b1) {
    asm volatile(
        "mma.sync.aligned.m16n8k8.row.col.f32.tf32.tf32.f32 "
        "{%0,%1,%2,%3}, {%4,%5,%6,%7}, {%8,%9}, {%0,%1,%2,%3};\n"
        : "+f"(c[0]), "+f"(c[1]), "+f"(c[2]), "+f"(c[3])
        : "r"(a0), "r"(a1), "r"(a2), "r"(a3), "r"(b0), "r"(b1));
}

// ---------------- fp16 helpers (attention) ----------------
__device__ __forceinline__ void mma_f16(float c[4], uint32_t a0, uint32_t a1,
                                        uint32_t a2, uint32_t a3,
                                        uint32_t b0, uint32_t b1) {
    asm volatile(
        "mma.sync.aligned.m16n8k16.row.col.f32.f16.f16.f32 "
        "{%0,%1,%2,%3}, {%4,%5,%6,%7}, {%8,%9}, {%0,%1,%2,%3};\n"
        : "+f"(c[0]), "+f"(c[1]), "+f"(c[2]), "+f"(c[3])
        : "r"(a0), "r"(a1), "r"(a2), "r"(a3), "r"(b0), "r"(b1));
}
__device__ __forceinline__ uint32_t packh2(float lo, float hi) {
    uint32_t r;
    asm("cvt.rn.f16x2.f32 %0, %2, %1;" : "=r"(r) : "f"(lo), "f"(hi));
    return r;
}
__device__ __forceinline__ void ldsm_x4_t(uint32_t r[4], const __half* p) {
    uint32_t a = (uint32_t)__cvta_generic_to_shared(p);
    asm volatile("ldmatrix.sync.aligned.m8n8.x4.trans.shared.b16 {%0,%1,%2,%3}, [%4];"
                 : "=r"(r[0]), "=r"(r[1]), "=r"(r[2]), "=r"(r[3]) : "r"(a));
}

// ---------------- tf32 tensor-core GEMM (unchanged) ----------------
#define BM 128
#define BN 128
#define BK 32
#define LDT 36

__global__ __launch_bounds__(256)
void gemm_tf32(const float* __restrict__ A, const float* __restrict__ Bw,
               const float* __restrict__ bias, float* __restrict__ C,
               int N, int K)
{
    __shared__ float As[BM * LDT];
    __shared__ float Bs[BN * LDT];

    const int tid  = threadIdx.x;
    const int lane = tid & 31;
    const int wid  = tid >> 5;
    const int g = lane >> 2;
    const int t = lane & 3;
    const int wm = wid >> 2;
    const int wn = wid & 3;
    const int row0 = blockIdx.y * BM;
    const int col0 = blockIdx.x * BN;

    const int kg = tid & 7;
    const int lr = tid >> 3;
    const float* Ag = A  + (size_t)(row0 + lr) * K + kg * 4;
    const float* Bg = Bw + (size_t)(col0 + lr) * K + kg * 4;

    float c[4][4][4];
#pragma unroll
    for (int mt = 0; mt < 4; mt++)
#pragma unroll
        for (int nt = 0; nt < 4; nt++)
#pragma unroll
            for (int r = 0; r < 4; r++) c[mt][nt][r] = 0.f;

    const float* Awp = &As[(wm * 64) * LDT];
    const float* Bwp = &Bs[(wn * 32) * LDT];

    for (int kp = 0; kp < K; kp += BK) {
        float4 av[4], bv[4];
#pragma unroll
        for (int i = 0; i < 4; i++) {
            av[i] = *(const float4*)(Ag + (size_t)i * 32 * K + kp);
            bv[i] = *(const float4*)(Bg + (size_t)i * 32 * K + kp);
        }
#pragma unroll
        for (int i = 0; i < 4; i++) {
            av[i].x = __uint_as_float(f2tf32(av[i].x));
            av[i].y = __uint_as_float(f2tf32(av[i].y));
            av[i].z = __uint_as_float(f2tf32(av[i].z));
            av[i].w = __uint_as_float(f2tf32(av[i].w));
            bv[i].x = __uint_as_float(f2tf32(bv[i].x));
            bv[i].y = __uint_as_float(f2tf32(bv[i].y));
            bv[i].z = __uint_as_float(f2tf32(bv[i].z));
            bv[i].w = __uint_as_float(f2tf32(bv[i].w));
        }
        __syncthreads();
#pragma unroll
        for (int i = 0; i < 4; i++) {
            *(float4*)&As[(lr + i * 32) * LDT + kg * 4] = av[i];
            *(float4*)&Bs[(lr + i * 32) * LDT + kg * 4] = bv[i];
        }
        __syncthreads();

#pragma unroll
        for (int kq = 0; kq < BK; kq += 8) {
            uint32_t af[4][4], bf[4][2];
#pragma unroll
            for (int mt = 0; mt < 4; mt++) {
                const float* ap = Awp + (mt * 16 + g) * LDT + kq + t;
                af[mt][0] = __float_as_uint(ap[0]);
                af[mt][1] = __float_as_uint(ap[8 * LDT]);
                af[mt][2] = __float_as_uint(ap[4]);
                af[mt][3] = __float_as_uint(ap[8 * LDT + 4]);
            }
#pragma unroll
            for (int nt = 0; nt < 4; nt++) {
                const float* bp = Bwp + (nt * 8 + g) * LDT + kq + t;
                bf[nt][0] = __float_as_uint(bp[0]);
                bf[nt][1] = __float_as_uint(bp[4]);
            }
#pragma unroll
            for (int mt = 0; mt < 4; mt++)
#pragma unroll
                for (int nt = 0; nt < 4; nt++)
                    mma_tf32(c[mt][nt], af[mt][0], af[mt][1], af[mt][2], af[mt][3],
                             bf[nt][0], bf[nt][1]);
        }
    }

#pragma unroll
    for (int mt = 0; mt < 4; mt++) {
        int row = row0 + wm * 64 + mt * 16 + g;
#pragma unroll
        for (int nt = 0; nt < 4; nt++) {
            int col = col0 + wn * 32 + nt * 8 + 2 * t;
            float b0 = bias[col], b1 = bias[col + 1];
            float2 v0 = make_float2(c[mt][nt][0] + b0, c[mt][nt][1] + b1);
            float2 v1 = make_float2(c[mt][nt][2] + b0, c[mt][nt][3] + b1);
            *(float2*)&C[(size_t)row * N + col] = v0;
            *(float2*)&C[(size_t)(row + 8) * N + col] = v1;
        }
    }
}

// ---------------- fp16-split tensor-core flash attention ----------------
// CTA: 128 queries x 64-key tiles, 8 warps (16 query rows each).
// QK^T: 3-term fp16 split (near-fp32). PV: P fp16, V 2-term split.
#define SH 72                       // smem row stride in halves (144 B)
#define OQH 0
#define OQL (128 * SH)
#define OKH (2 * 128 * SH)
#define OKL (OKH + 64 * SH)
#define OVH (OKL + 64 * SH)
#define OVL (OVH + 64 * SH)
#define OPS (OVL + 64 * SH)
#define SMH_TOT (OPS + 128 * SH)    // 46080 halves = 92160 B

__global__ __launch_bounds__(256, 2)
void attn_fp16(const float* __restrict__ qkv, float* __restrict__ attn_out)
{
    extern __shared__ __half smh[];

    const int tid  = threadIdx.x;
    const int lane = tid & 31;
    const int w = tid >> 5;
    const int g = lane >> 2;
    const int t = lane & 3;
    const int b = blockIdx.y >> 4, h = blockIdx.y & 15;
    const int qt = (int)gridDim.x - 1 - (int)blockIdx.x;   // heavy CTAs first
    const int q0 = qt * 128;
    const float* base = qkv + (size_t)b * SEQ * QKV_N + h * (3 * HEAD_DIM);
    const float SC = 0.125f * 1.4426950408889634f;   // 1/sqrt(hd) * log2(e)

    // ---- load Q tile, split into fp16 hi/lo ----
#pragma unroll
    for (int i = 0; i < 8; i++) {
        int idx = tid + i * 256;
        int r = idx >> 4, c4 = (idx & 15) << 2;
        float4 q = *(const float4*)(base + (size_t)(q0 + r) * QKV_N + c4);
        float f[4] = {q.x * SC, q.y * SC, q.z * SC, q.w * SC};
        float hh[4], ll[4];
#pragma unroll
        for (int e = 0; e < 4; e++) {
            hh[e] = __half2float(__float2half_rn(f[e]));
            ll[e] = f[e] - hh[e];
        }
        uint32_t* ph = (uint32_t*)&smh[OQH + r * SH + c4];
        uint32_t* pl = (uint32_t*)&smh[OQL + r * SH + c4];
        ph[0] = packh2(hh[0], hh[1]); ph[1] = packh2(hh[2], hh[3]);
        pl[0] = packh2(ll[0], ll[1]); pl[1] = packh2(ll[2], ll[3]);
    }

    float o[8][4];
#pragma unroll
    for (int nt = 0; nt < 8; nt++)
#pragma unroll
        for (int r = 0; r < 4; r++) o[nt][r] = 0.f;
    float m0 = -1e30f, m1 = -1e30f, l0 = 0.f, l1 = 0.f;

    const int wr = w * 16;
    const int myrow = q0 + wr;
    const int rowg0 = myrow + g, rowg1 = myrow + g + 8;
    const int nkt = qt * 2 + 2;

    // ldmatrix per-thread source row/col selectors
    const int lr7  = lane & 7;
    const int ksel = (lane >> 3) & 1;
    const int nsel = lane >> 4;

    for (int j = 0; j < nkt; j++) {
        const int k0 = j * 64;
        // register prefetch of K/V tile
        float4 kk[4], vv[4];
#pragma unroll
        for (int i = 0; i < 4; i++) {
            int idx = tid + i * 256;
            int r = idx >> 4, c4 = (idx & 15) << 2;
            const float* rp = base + (size_t)(k0 + r) * QKV_N + c4;
            kk[i] = *(const float4*)(rp + HEAD_DIM);
            vv[i] = *(const float4*)(rp + 2 * HEAD_DIM);
        }
        __syncthreads();   // previous tile fully consumed
#pragma unroll
        for (int i = 0; i < 4; i++) {
            int idx = tid + i * 256;
            int r = idx >> 4, c4 = (idx & 15) << 2;
            float kf[4] = {kk[i].x, kk[i].y, kk[i].z, kk[i].w};
            float vf[4] = {vv[i].x, vv[i].y, vv[i].z, vv[i].w};
            float kh[4], kl[4], vh[4], vl[4];
#pragma unroll
            for (int e = 0; e < 4; e++) {
                kh[e] = __half2float(__float2half_rn(kf[e])); kl[e] = kf[e] - kh[e];
                vh[e] = __half2float(__float2half_rn(vf[e])); vl[e] = vf[e] - vh[e];
            }
            uint32_t* p;
            p = (uint32_t*)&smh[OKH + r * SH + c4];
            p[0] = packh2(kh[0], kh[1]); p[1] = packh2(kh[2], kh[3]);
            p = (uint32_t*)&smh[OKL + r * SH + c4];
            p[0] = packh2(kl[0], kl[1]); p[1] = packh2(kl[2], kl[3]);
            p = (uint32_t*)&smh[OVH + r * SH + c4];
            p[0] = packh2(vh[0], vh[1]); p[1] = packh2(vh[2], vh[3]);
            p = (uint32_t*)&smh[OVL + r * SH + c4];
            p[0] = packh2(vl[0], vl[1]); p[1] = packh2(vl[2], vl[3]);
        }
        __syncthreads();

        if (k0 <= myrow + 15) {   // not fully masked for this warp
            // ---- S = Q K^T  (3-term fp16 split) ----
            float s[8][4];
#pragma unroll
            for (int nt = 0; nt < 8; nt++)
#pragma unroll
                for (int r = 0; r < 4; r++) s[nt][r] = 0.f;

#pragma unroll
            for (int kq = 0; kq < 4; kq++) {
                const int kc = kq * 16;
                const int a_lo = (wr + g) * SH + kc + 2 * t;
                const int a_hi = (wr + g + 8) * SH + kc + 2 * t;
                uint32_t ah0 = *(uint32_t*)&smh[OQH + a_lo];
                uint32_t ah1 = *(uint32_t*)&smh[OQH + a_hi];
                uint32_t ah2 = *(uint32_t*)&smh[OQH + a_lo + 8];
                uint32_t ah3 = *(uint32_t*)&smh[OQH + a_hi + 8];
                uint32_t al0 = *(uint32_t*)&smh[OQL + a_lo];
                uint32_t al1 = *(uint32_t*)&smh[OQL + a_hi];
                uint32_t al2 = *(uint32_t*)&smh[OQL + a_lo + 8];
                uint32_t al3 = *(uint32_t*)&smh[OQL + a_hi + 8];
#pragma unroll
                for (int nt = 0; nt < 8; nt++) {
                    const int bidx = (nt * 8 + g) * SH + kc + 2 * t;
                    uint32_t bh0 = *(uint32_t*)&smh[OKH + bidx];
                    uint32_t bh1 = *(uint32_t*)&smh[OKH + bidx + 8];
                    uint32_t bl0 = *(uint32_t*)&smh[OKL + bidx];
                    uint32_t bl1 = *(uint32_t*)&smh[OKL + bidx + 8];
                    mma_f16(s[nt], ah0, ah1, ah2, ah3, bh0, bh1);
                    mma_f16(s[nt], al0, al1, al2, al3, bh0, bh1);
                    mma_f16(s[nt], ah0, ah1, ah2, ah3, bl0, bl1);
                }
            }

            // ---- causal mask (diagonal-straddling tiles only) ----
            if (k0 + 63 > myrow) {
#pragma unroll
                for (int nt = 0; nt < 8; nt++) {
                    int c = k0 + nt * 8 + 2 * t;
                    if (c > rowg0)     s[nt][0] = -1e30f;
                    if (c + 1 > rowg0) s[nt][1] = -1e30f;
                    if (c > rowg1)     s[nt][2] = -1e30f;
                    if (c + 1 > rowg1) s[nt][3] = -1e30f;
                }
            }

            // ---- online softmax (exp2 domain), P -> fp16 smem ----
            float rm0 = -1e30f, rm1 = -1e30f;
#pragma unroll
            for (int nt = 0; nt < 8; nt++) {
                rm0 = fmaxf(rm0, fmaxf(s[nt][0], s[nt][1]));
                rm1 = fmaxf(rm1, fmaxf(s[nt][2], s[nt][3]));
            }
            rm0 = fmaxf(rm0, __shfl_xor_sync(0xffffffffu, rm0, 1));
            rm0 = fmaxf(rm0, __shfl_xor_sync(0xffffffffu, rm0, 2));
            rm1 = fmaxf(rm1, __shfl_xor_sync(0xffffffffu, rm1, 1));
            rm1 = fmaxf(rm1, __shfl_xor_sync(0xffffffffu, rm1, 2));
            float mn0 = fmaxf(m0, rm0), mn1 = fmaxf(m1, rm1);
            float alp0 = exp2f(m0 - mn0), alp1 = exp2f(m1 - mn1);
            float rs0 = 0.f, rs1 = 0.f;
#pragma unroll
            for (int nt = 0; nt < 8; nt++) {
                s[nt][0] = exp2f(s[nt][0] - mn0);
                s[nt][1] = exp2f(s[nt][1] - mn0);
                s[nt][2] = exp2f(s[nt][2] - mn1);
                s[nt][3] = exp2f(s[nt][3] - mn1);
                rs0 += s[nt][0] + s[nt][1];
                rs1 += s[nt][2] + s[nt][3];
                *(uint32_t*)&smh[OPS + (wr + g) * SH + nt * 8 + 2 * t] =
                    packh2(s[nt][0], s[nt][1]);
                *(uint32_t*)&smh[OPS + (wr + g + 8) * SH + nt * 8 + 2 * t] =
                    packh2(s[nt][2], s[nt][3]);
            }
            rs0 += __shfl_xor_sync(0xffffffffu, rs0, 1);
            rs0 += __shfl_xor_sync(0xffffffffu, rs0, 2);
            rs1 += __shfl_xor_sync(0xffffffffu, rs1, 1);
            rs1 += __shfl_xor_sync(0xffffffffu, rs1, 2);
            l0 = l0 * alp0 + rs0;  l1 = l1 * alp1 + rs1;
            m0 = mn0;  m1 = mn1;
#pragma unroll
            for (int nt = 0; nt < 8; nt++) {
                o[nt][0] *= alp0; o[nt][1] *= alp0;
                o[nt][2] *= alp1; o[nt][3] *= alp1;
            }
            __syncwarp();   // P stores visible to warp

            // ---- O += P V  (P fp16, V 2-term split; V^T via ldmatrix.trans) ----
#pragma unroll
            for (int kq = 0; kq < 4; kq++) {
                const int kc = kq * 16;
                const int a_lo = (wr + g) * SH + kc + 2 * t;
                const int a_hi = (wr + g + 8) * SH + kc + 2 * t;
                uint32_t pa0 = *(uint32_t*)&smh[OPS + a_lo];
                uint32_t pa1 = *(uint32_t*)&smh[OPS + a_hi];
                uint32_t pa2 = *(uint32_t*)&smh[OPS + a_lo + 8];
                uint32_t pa3 = *(uint32_t*)&smh[OPS + a_hi + 8];
                const int vrow = (kc + lr7 + 8 * ksel) * SH + nsel * 8;
#pragma unroll
                for (int np = 0; np < 4; np++) {
                    uint32_t bh[4], bl[4];
                    ldsm_x4_t(bh, &smh[OVH + vrow + np * 16]);
                    ldsm_x4_t(bl, &smh[OVL + vrow + np * 16]);
                    mma_f16(o[np * 2],     pa0, pa1, pa2, pa3, bh[0], bh[1]);
                    mma_f16(o[np * 2],     pa0, pa1, pa2, pa3, bl[0], bl[1]);
                    mma_f16(o[np * 2 + 1], pa0, pa1, pa2, pa3, bh[2], bh[3]);
                    mma_f16(o[np * 2 + 1], pa0, pa1, pa2, pa3, bl[2], bl[3]);
                }
            }
            __syncwarp();
        }
    }

    // ---- normalize + write [B,H,S,hd] ----
    float inv0 = 1.0f / l0, inv1 = 1.0f / l1;
    float* op = attn_out + ((size_t)b * NUM_HEADS + h) * SEQ * HEAD_DIM;
#pragma unroll
    for (int nt = 0; nt < 8; nt++) {
        int c = nt * 8 + 2 * t;
        *(float2*)&op[(size_t)rowg0 * HEAD_DIM + c] =
            make_float2(o[nt][0] * inv0, o[nt][1] * inv0);
        *(float2*)&op[(size_t)rowg1 * HEAD_DIM + c] =
            make_float2(o[nt][2] * inv1, o[nt][3] * inv1);
    }
}

// ---------------- launch ----------------
extern "C" void kernel_launch(void* const* d_in, const int* in_sizes, int n_in,
                              void* d_out, int out_size)
{
    const float* x    = (const float*)d_in[0];
    const float* Wqkv = (const float*)d_in[1];
    const float* bqkv = (const float*)d_in[2];
    const float* Wo   = (const float*)d_in[3];
    const float* bo   = (const float*)d_in[4];
    float* out = (float*)d_out;

    float* qkv_ptr = nullptr;
    float* attn_ptr = nullptr;
    cudaGetSymbolAddress((void**)&qkv_ptr, g_qkv);
    cudaGetSymbolAddress((void**)&attn_ptr, g_attn);

    const int attn_smem = SMH_TOT * (int)sizeof(__half);   // 92160 B
    cudaFuncSetAttribute(attn_fp16, cudaFuncAttributeMaxDynamicSharedMemorySize, attn_smem);

    // 1) qkv = x @ Wqkv^T + bqkv   (tf32 tensor cores)
    gemm_tf32<<<dim3(QKV_N / BN, M_TOT / BM), 256>>>(x, Wqkv, bqkv, qkv_ptr, QKV_N, D_MODEL);
    // 2) causal flash attention (fp16-split tensor cores)
    attn_fp16<<<dim3(SEQ / 128, BATCH * NUM_HEADS), 256, attn_smem>>>(qkv_ptr, attn_ptr);
    // 3) out = attn @ Wo^T + bo    (tf32 tensor cores)
    gemm_tf32<<<dim3(D_MODEL / BN, M_TOT / BM), 256>>>(attn_ptr, Wo, bo, out, D_MODEL, D_MODEL);
}